// round 1
// baseline (speedup 1.0000x reference)
#include <cuda_runtime.h>
#include <cuda_bf16.h>

// Problem shape (fixed by reference setup_inputs): B=8, C=16, H=W=384.
#define BB 8
#define CC 16
#define HW 147456            // 384*384
#define NPLANE (BB*CC)       // 128
#define SPLIT 8              // chunks per plane
#define CHUNK (HW/SPLIT)     // 18432
#define TPB 256
#define NBLK (NPLANE*SPLIT)  // 1024
#define ITERS (CHUNK/4/TPB)  // 18 float4 per thread

#define SMOOTH 1e-6f
#define ALPHA 0.05f

// Per-block partials: [m1, sum_d2, d1, max_t, max_p]
__device__ float g_partial[NBLK * 5];

__global__ void __launch_bounds__(TPB, 2)
partial_kernel(const float* __restrict__ net,
               const float* __restrict__ tgt,
               const float* __restrict__ mpos) {
    const int blk   = blockIdx.x;
    const int plane = blk >> 3;       // / SPLIT
    const int chunk = blk & 7;        // % SPLIT
    const size_t base = (size_t)plane * HW + (size_t)chunk * CHUNK;

    const float4* __restrict__ n4 = (const float4*)(net  + base);
    const float4* __restrict__ t4 = (const float4*)(tgt  + base);
    const float4* __restrict__ p4 = (const float4*)(mpos + base);

    const int tid = threadIdx.x;

    float m1 = 0.f, sd = 0.f, d1 = 0.f, mt = 0.f, mp = 0.f;

#pragma unroll
    for (int i = 0; i < ITERS; i++) {
        const int idx = i * TPB + tid;
        float4 n = n4[idx];
        float4 t = t4[idx];
        float4 p = p4[idx];

        float d, d2;
        d = t.x - n.x; d2 = d * d; sd += d2; m1 += d2 * t.x; d1 += t.x;
        mt = fmaxf(mt, t.x); mp = fmaxf(mp, p.x);
        d = t.y - n.y; d2 = d * d; sd += d2; m1 += d2 * t.y; d1 += t.y;
        mt = fmaxf(mt, t.y); mp = fmaxf(mp, p.y);
        d = t.z - n.z; d2 = d * d; sd += d2; m1 += d2 * t.z; d1 += t.z;
        mt = fmaxf(mt, t.z); mp = fmaxf(mp, p.z);
        d = t.w - n.w; d2 = d * d; sd += d2; m1 += d2 * t.w; d1 += t.w;
        mt = fmaxf(mt, t.w); mp = fmaxf(mp, p.w);
    }

    // Warp reduce 5 values
    const unsigned FULL = 0xFFFFFFFFu;
#pragma unroll
    for (int off = 16; off > 0; off >>= 1) {
        m1 += __shfl_down_sync(FULL, m1, off);
        sd += __shfl_down_sync(FULL, sd, off);
        d1 += __shfl_down_sync(FULL, d1, off);
        mt = fmaxf(mt, __shfl_down_sync(FULL, mt, off));
        mp = fmaxf(mp, __shfl_down_sync(FULL, mp, off));
    }

    __shared__ float sh[5][TPB / 32];
    const int lane = tid & 31, wid = tid >> 5;
    if (lane == 0) {
        sh[0][wid] = m1; sh[1][wid] = sd; sh[2][wid] = d1;
        sh[3][wid] = mt; sh[4][wid] = mp;
    }
    __syncthreads();

    if (wid == 0) {
        const int NW = TPB / 32;
        m1 = (lane < NW) ? sh[0][lane] : 0.f;
        sd = (lane < NW) ? sh[1][lane] : 0.f;
        d1 = (lane < NW) ? sh[2][lane] : 0.f;
        mt = (lane < NW) ? sh[3][lane] : 0.f;
        mp = (lane < NW) ? sh[4][lane] : 0.f;
#pragma unroll
        for (int off = 4; off > 0; off >>= 1) {
            m1 += __shfl_down_sync(FULL, m1, off);
            sd += __shfl_down_sync(FULL, sd, off);
            d1 += __shfl_down_sync(FULL, d1, off);
            mt = fmaxf(mt, __shfl_down_sync(FULL, mt, off));
            mp = fmaxf(mp, __shfl_down_sync(FULL, mp, off));
        }
        if (lane == 0) {
            float* out = &g_partial[blk * 5];
            out[0] = m1; out[1] = sd; out[2] = d1; out[3] = mt; out[4] = mp;
        }
    }
}

__global__ void finalize_kernel(float* __restrict__ out) {
    const int t = threadIdx.x;  // plane id 0..127
    float m1 = 0.f, sd = 0.f, d1 = 0.f, mt = 0.f, mp = 0.f;
#pragma unroll
    for (int s = 0; s < SPLIT; s++) {
        const float* p = &g_partial[(t * SPLIT + s) * 5];
        m1 += p[0]; sd += p[1]; d1 += p[2];
        mt = fmaxf(mt, p[3]); mp = fmaxf(mp, p[4]);
    }
    float m2 = sd - m1;
    float d2 = (float)HW - d1;
    float loss = ALPHA * m1 / (d1 + SMOOTH) + (1.0f - ALPHA) * m2 / (d2 + SMOOTH);
    bool active = !((mt == 0.f) && (mp == 0.f));
    float lv = active ? loss : 0.f;

    __shared__ float losses[NPLANE];
    __shared__ float img[BB];
    losses[t] = lv;
    __syncthreads();

    if (t < BB) {
        float sum = 0.f;
        int cnt = 0;
        for (int c = 0; c < CC; c++) {
            float v = losses[t * CC + c];
            sum += v;
            cnt += (v != 0.f) ? 1 : 0;
        }
        img[t] = sum / (float)cnt;
    }
    __syncthreads();

    if (t == 0) {
        float s = 0.f;
        for (int b = 0; b < BB; b++) s += img[b];
        out[0] = s / (float)BB;
    }
}

extern "C" void kernel_launch(void* const* d_in, const int* in_sizes, int n_in,
                              void* d_out, int out_size) {
    const float* net  = (const float*)d_in[0];
    const float* tgt  = (const float*)d_in[1];
    const float* mpos = (const float*)d_in[2];
    float* out = (float*)d_out;

    partial_kernel<<<NBLK, TPB>>>(net, tgt, mpos);
    finalize_kernel<<<1, NPLANE>>>(out);
}

// round 2
// speedup vs baseline: 1.0073x; 1.0073x over previous
#include <cuda_runtime.h>
#include <cuda_bf16.h>

// Problem shape (fixed by reference setup_inputs): B=8, C=16, H=W=384.
#define BB 8
#define CC 16
#define HW 147456            // 384*384
#define NPLANE (BB*CC)       // 128
#define SPLIT 8              // chunks per plane
#define CHUNK (HW/SPLIT)     // 18432
#define TPB 256
#define NBLK (NPLANE*SPLIT)  // 1024
#define ITERS (CHUNK/4/TPB)  // 18 float4 per thread

#define SMOOTH 1e-6f
#define ALPHA 0.05f

// Per-block partials: [m1, sum_d2, d1, max_t, max_p]
__device__ float g_partial[NBLK * 5];
__device__ int   g_counter = 0;   // reset to 0 by the last block each call

__global__ void __launch_bounds__(TPB, 2)
fused_loss_kernel(const float* __restrict__ net,
                  const float* __restrict__ tgt,
                  const float* __restrict__ mpos,
                  float* __restrict__ out) {
    const int blk   = blockIdx.x;
    const int plane = blk >> 3;       // / SPLIT
    const int chunk = blk & 7;        // % SPLIT
    const size_t base = (size_t)plane * HW + (size_t)chunk * CHUNK;

    const float4* __restrict__ n4 = (const float4*)(net  + base);
    const float4* __restrict__ t4 = (const float4*)(tgt  + base);
    const float4* __restrict__ p4 = (const float4*)(mpos + base);

    const int tid = threadIdx.x;

    float m1 = 0.f, sd = 0.f, d1 = 0.f, mt = 0.f, mp = 0.f;

#pragma unroll
    for (int i = 0; i < ITERS; i++) {
        const int idx = i * TPB + tid;
        float4 n = n4[idx];
        float4 t = t4[idx];
        float4 p = p4[idx];

        float d, d2;
        d = t.x - n.x; d2 = d * d; sd += d2; m1 += d2 * t.x; d1 += t.x;
        mt = fmaxf(mt, t.x); mp = fmaxf(mp, p.x);
        d = t.y - n.y; d2 = d * d; sd += d2; m1 += d2 * t.y; d1 += t.y;
        mt = fmaxf(mt, t.y); mp = fmaxf(mp, p.y);
        d = t.z - n.z; d2 = d * d; sd += d2; m1 += d2 * t.z; d1 += t.z;
        mt = fmaxf(mt, t.z); mp = fmaxf(mp, p.z);
        d = t.w - n.w; d2 = d * d; sd += d2; m1 += d2 * t.w; d1 += t.w;
        mt = fmaxf(mt, t.w); mp = fmaxf(mp, p.w);
    }

    // Warp reduce 5 values
    const unsigned FULL = 0xFFFFFFFFu;
#pragma unroll
    for (int off = 16; off > 0; off >>= 1) {
        m1 += __shfl_down_sync(FULL, m1, off);
        sd += __shfl_down_sync(FULL, sd, off);
        d1 += __shfl_down_sync(FULL, d1, off);
        mt = fmaxf(mt, __shfl_down_sync(FULL, mt, off));
        mp = fmaxf(mp, __shfl_down_sync(FULL, mp, off));
    }

    __shared__ float sh[5][TPB / 32];
    const int lane = tid & 31, wid = tid >> 5;
    if (lane == 0) {
        sh[0][wid] = m1; sh[1][wid] = sd; sh[2][wid] = d1;
        sh[3][wid] = mt; sh[4][wid] = mp;
    }
    __syncthreads();

    __shared__ bool s_last;
    if (tid == 0) {
        const int NW = TPB / 32;
        float a0 = 0.f, a1 = 0.f, a2 = 0.f, a3 = 0.f, a4 = 0.f;
#pragma unroll
        for (int w = 0; w < NW; w++) {
            a0 += sh[0][w]; a1 += sh[1][w]; a2 += sh[2][w];
            a3 = fmaxf(a3, sh[3][w]); a4 = fmaxf(a4, sh[4][w]);
        }
        float* p = &g_partial[blk * 5];
        p[0] = a0; p[1] = a1; p[2] = a2; p[3] = a3; p[4] = a4;
        __threadfence();
        int prev = atomicAdd(&g_counter, 1);
        s_last = (prev == NBLK - 1);
    }
    __syncthreads();

    if (!s_last) return;

    // ---- Last block: finalize ----
    if (tid == 0) g_counter = 0;     // reset for next graph replay
    __threadfence();                 // make sure partial reads see all writers

    __shared__ float losses[NPLANE];
    __shared__ float img[BB];

    if (tid < NPLANE) {
        float m1f = 0.f, sdf = 0.f, d1f = 0.f, mtf = 0.f, mpf = 0.f;
#pragma unroll
        for (int s = 0; s < SPLIT; s++) {
            const float* p = &g_partial[(tid * SPLIT + s) * 5];
            m1f += p[0]; sdf += p[1]; d1f += p[2];
            mtf = fmaxf(mtf, p[3]); mpf = fmaxf(mpf, p[4]);
        }
        float m2f = sdf - m1f;
        float d2f = (float)HW - d1f;
        float loss = ALPHA * m1f / (d1f + SMOOTH) + (1.0f - ALPHA) * m2f / (d2f + SMOOTH);
        bool active = !((mtf == 0.f) && (mpf == 0.f));
        losses[tid] = active ? loss : 0.f;
    }
    __syncthreads();

    if (tid < BB) {
        float sum = 0.f;
        int cnt = 0;
#pragma unroll
        for (int c = 0; c < CC; c++) {
            float v = losses[tid * CC + c];
            sum += v;
            cnt += (v != 0.f) ? 1 : 0;
        }
        img[tid] = sum / (float)cnt;
    }
    __syncthreads();

    if (tid == 0) {
        float s = 0.f;
#pragma unroll
        for (int b = 0; b < BB; b++) s += img[b];
        out[0] = s / (float)BB;
    }
}

extern "C" void kernel_launch(void* const* d_in, const int* in_sizes, int n_in,
                              void* d_out, int out_size) {
    const float* net  = (const float*)d_in[0];
    const float* tgt  = (const float*)d_in[1];
    const float* mpos = (const float*)d_in[2];
    float* out = (float*)d_out;

    fused_loss_kernel<<<NBLK, TPB>>>(net, tgt, mpos, out);
}